// round 9
// baseline (speedup 1.0000x reference)
#include <cuda_runtime.h>
#include <cstdint>
#include <cstddef>

// ---------------------------------------------------------------------------
// MPConv fused GNN edge-MLP + scatter on GB300 (sm_103a)
// R9 = R8 (edge kernel untouched) + FFMA2 precompute + FFMA2 node kernel +
//      dtype-detect folded into precompute block 0.
// ---------------------------------------------------------------------------

#define NODES_MAX 100000
#define E_TILE    128
#define NTHREADS  256

typedef unsigned long long ull_t;

__device__ __align__(16) float g_AB[(size_t)NODES_MAX * 128];   // A||B per node
__device__ __align__(16) float g_G[(size_t)NODES_MAX * 64];     // scattered g sums
__device__ __align__(16) float g_degf[NODES_MAX];               // edge counts
__device__ int g_idx64;

__device__ __forceinline__ float gelu_exact(float v) {
    return 0.5f * v * (1.0f + erff(v * 0.70710678118654752440f));
}

__device__ __forceinline__ void fma2(ull_t& d, ull_t a, ull_t b) {
    asm("fma.rn.f32x2 %0, %1, %2, %0;" : "+l"(d) : "l"(a), "l"(b));
}
#define UNPK(lo, hi, v) asm("mov.b64 {%0,%1}, %2;" : "=f"(lo), "=f"(hi) : "l"(v))
#define DUP(d, f)       asm("mov.b64 %0, {%1, %1};" : "=l"(d) : "f"(f))

__device__ __forceinline__ int load_edge_idx(const void* ei, long long pos, int idx64) {
    if (idx64) return (int)((const long long*)ei)[pos];
    return ((const int*)ei)[pos];
}

// ---------------------------------------------------------------------------
// Precompute g_AB with f32x2 (channel-pair) math; zero this block's G/deg
// slice; block 0 also runs the edge_index dtype detect.
// 64 nodes x 128 ch per CTA. Thread: c0=(t&15)*8, n0=(t>>4)*4.
// dyn smem: xT[64][65] + pad + Wc[64][128]
__global__ void __launch_bounds__(NTHREADS, 2)
precompute_kernel(const float* __restrict__ x,
                  const float* __restrict__ W1,
                  const float* __restrict__ b1,
                  const void* __restrict__ edge_index,
                  int N) {
    extern __shared__ float sm[];
    float* xT = sm;                  // [k][node], stride 65
    float* Wc = sm + 64 * 65 + 4;    // [k][c] 64x128

    int t = threadIdx.x;
    int n_base = blockIdx.x * 64;

    // dtype detect (block 0): int32 misread as int64 escapes [0,N) w.h.p.
    if (blockIdx.x == 0 && t < 128) {
        long long v = ((const long long*)edge_index)[t];
        unsigned bad = __ballot_sync(0xffffffffu, v < 0 || v >= (long long)N);
        // cross-warp combine via atomic on the global flag
        if ((t & 31) == 0) {
            if (t == 0) g_idx64 = 1;               // provisional
        }
        __syncwarp();
        if (bad && (t & 31) == 0) atomicExch(&g_idx64, 0);
        if (t == 0 && !bad) atomicCAS(&g_idx64, 1, 1);  // ensure written
    }

    // zero scratch for this block's nodes
    {
        float4 z4 = make_float4(0.f, 0.f, 0.f, 0.f);
#pragma unroll
        for (int it = 0; it < 4; ++it) {
            int idx = t + it * NTHREADS;        // 0..1023 float4 slots
            int node = idx >> 4, q = idx & 15;
            int gn = n_base + node;
            if (gn < N) ((float4*)g_G)[(size_t)gn * 16 + q] = z4;
        }
        if (t < 64 && n_base + t < N) g_degf[n_base + t] = 0.f;
    }

    // stage Wc = [W1[0:64] | W1[64:128]] rows, and xT transposed
#pragma unroll
    for (int it = 0; it < 32; ++it) {
        int idx = t + it * NTHREADS;
        int k = idx >> 7, c = idx & 127;
        Wc[idx] = (c < 64) ? W1[k * 64 + c] : W1[(64 + k) * 64 + (c - 64)];
    }
#pragma unroll
    for (int it = 0; it < 16; ++it) {
        int idx = t + it * NTHREADS;
        int node = idx >> 6, k = idx & 63;
        int gn = n_base + node;
        xT[k * 65 + node] = (gn < N) ? x[(size_t)gn * 64 + k] : 0.f;
    }
    __syncthreads();

    int tx = t & 15, ty = t >> 4;
    int c0 = tx * 8, n0 = ty * 4;

    // acc[n*4+cp]: node n (0..3), channel-pair cp (0..3) => ch (c0+2cp, +1)
    ull_t acc[16];
    {
        ull_t binit[4] = {0ull, 0ull, 0ull, 0ull};
        if (c0 < 64) {
            const ull_t* bp = (const ull_t*)&b1[c0];
            ulonglong2 b01 = *(const ulonglong2*)(bp);
            ulonglong2 b23 = *(const ulonglong2*)(bp + 2);
            binit[0] = b01.x; binit[1] = b01.y;
            binit[2] = b23.x; binit[3] = b23.y;
        }
#pragma unroll
        for (int n = 0; n < 4; ++n)
#pragma unroll
            for (int cp = 0; cp < 4; ++cp) acc[n * 4 + cp] = binit[cp];
    }

#pragma unroll 4
    for (int k = 0; k < 64; ++k) {
        const float* xp = &xT[k * 65 + n0];
        ull_t X0, X1, X2, X3;
        DUP(X0, xp[0]); DUP(X1, xp[1]); DUP(X2, xp[2]); DUP(X3, xp[3]);
        const ull_t* wp = (const ull_t*)&Wc[k * 128 + c0];
        ulonglong2 w01 = *(const ulonglong2*)(wp);
        ulonglong2 w23 = *(const ulonglong2*)(wp + 2);
        fma2(acc[ 0], X0, w01.x); fma2(acc[ 1], X0, w01.y);
        fma2(acc[ 2], X0, w23.x); fma2(acc[ 3], X0, w23.y);
        fma2(acc[ 4], X1, w01.x); fma2(acc[ 5], X1, w01.y);
        fma2(acc[ 6], X1, w23.x); fma2(acc[ 7], X1, w23.y);
        fma2(acc[ 8], X2, w01.x); fma2(acc[ 9], X2, w01.y);
        fma2(acc[10], X2, w23.x); fma2(acc[11], X2, w23.y);
        fma2(acc[12], X3, w01.x); fma2(acc[13], X3, w01.y);
        fma2(acc[14], X3, w23.x); fma2(acc[15], X3, w23.y);
    }

#pragma unroll
    for (int r = 0; r < 4; ++r) {
        int gn = n_base + n0 + r;
        if (gn < N) {
            ull_t* dst = (ull_t*)&g_AB[(size_t)gn * 128 + c0];
            ulonglong2 v01; v01.x = acc[r * 4 + 0]; v01.y = acc[r * 4 + 1];
            ulonglong2 v23; v23.x = acc[r * 4 + 2]; v23.y = acc[r * 4 + 3];
            *(ulonglong2*)(dst)     = v01;
            *(ulonglong2*)(dst + 2) = v23;
        }
    }
}

// ---------------------------------------------------------------------------
// Edge kernel (R8, unchanged). 128 edges/block, 256 threads, 4ch x 8edge.
// dyn smem (26112 B): iidx@0, jidx@512, W1p[32][64]@1024, eaT[32][132]@9216
__global__ void __launch_bounds__(NTHREADS, 3)
edge_kernel(const void* __restrict__ edge_index,
            const float* __restrict__ edge_attr,
            const float* __restrict__ W1,
            const float* __restrict__ gamma,
            const float* __restrict__ beta,
            int E) {
    extern __shared__ char smraw[];
    int*   iidx = (int*)smraw;
    int*   jidx = iidx + 128;
    float* W1p  = (float*)(smraw + 1024);
    float* eaT  = (float*)(smraw + 9216);

    int t = threadIdx.x;
    long long e_base = (long long)blockIdx.x * E_TILE;
    int idx64 = g_idx64;

    if (t < 128) iidx[t] = load_edge_idx(edge_index, e_base + t, idx64);
    else         jidx[t - 128] = load_edge_idx(edge_index, (long long)E + e_base + (t - 128), idx64);

    {
        const float4* src = (const float4*)(W1 + 128 * 64);
        float4* dst = (float4*)W1p;
        dst[t]       = src[t];
        dst[t + 256] = src[t + 256];
    }
    {
        const float4* ea4 = (const float4*)edge_attr;
#pragma unroll
        for (int it = 0; it < 4; ++it) {
            int slot = t + it * NTHREADS;           // 0..1023
            int e = slot >> 3, q = slot & 7;
            float4 v = ea4[e_base * 8 + slot];
            int k = q * 4;
            eaT[(k + 0) * 132 + e] = v.x;
            eaT[(k + 1) * 132 + e] = v.y;
            eaT[(k + 2) * 132 + e] = v.z;
            eaT[(k + 3) * 132 + e] = v.w;
        }
    }
    __syncthreads();

    int tx = t & 15, ty = t >> 4;
    int c0 = tx * 4, e0 = ty * 8;

    ull_t acc[16];
#pragma unroll
    for (int i = 0; i < 16; ++i) acc[i] = 0ull;

#pragma unroll 4
    for (int kk = 0; kk < 32; ++kk) {
        float4 w = *(const float4*)&W1p[kk * 64 + c0];
        ull_t W0, W1r, W2r, W3r;
        DUP(W0, w.x); DUP(W1r, w.y); DUP(W2r, w.z); DUP(W3r, w.w);
        const float* ap = eaT + kk * 132 + e0;
        ulonglong2 A01 = *(const ulonglong2*)(ap);
        ulonglong2 A23 = *(const ulonglong2*)(ap + 4);
        fma2(acc[ 0], A01.x, W0);  fma2(acc[ 1], A01.y, W0);
        fma2(acc[ 2], A23.x, W0);  fma2(acc[ 3], A23.y, W0);
        fma2(acc[ 4], A01.x, W1r); fma2(acc[ 5], A01.y, W1r);
        fma2(acc[ 6], A23.x, W1r); fma2(acc[ 7], A23.y, W1r);
        fma2(acc[ 8], A01.x, W2r); fma2(acc[ 9], A01.y, W2r);
        fma2(acc[10], A23.x, W2r); fma2(acc[11], A23.y, W2r);
        fma2(acc[12], A01.x, W3r); fma2(acc[13], A01.y, W3r);
        fma2(acc[14], A23.x, W3r); fma2(acc[15], A23.y, W3r);
    }

    float4 gmv = *(const float4*)&gamma[c0];
    float4 btv = *(const float4*)&beta[c0];
    const float4* AB4 = (const float4*)g_AB;

#pragma unroll
    for (int p = 0; p < 4; ++p) {
        int ea = e0 + 2 * p, eb = ea + 1;

        float va0, vb0, va1, vb1, va2, vb2, va3, vb3;
        UNPK(va0, vb0, acc[0 * 4 + p]);
        UNPK(va1, vb1, acc[1 * 4 + p]);
        UNPK(va2, vb2, acc[2 * 4 + p]);
        UNPK(va3, vb3, acc[3 * 4 + p]);

        {
            float4 Aa = AB4[(size_t)iidx[ea] * 32 + tx];
            float4 Ba = AB4[(size_t)jidx[ea] * 32 + 16 + tx];
            va0 += Aa.x + Ba.x; va1 += Aa.y + Ba.y;
            va2 += Aa.z + Ba.z; va3 += Aa.w + Ba.w;
        }
        {
            float4 Ab = AB4[(size_t)iidx[eb] * 32 + tx];
            float4 Bb = AB4[(size_t)jidx[eb] * 32 + 16 + tx];
            vb0 += Ab.x + Bb.x; vb1 += Ab.y + Bb.y;
            vb2 += Ab.z + Bb.z; vb3 += Ab.w + Bb.w;
        }

        float sa = va0 + va1 + va2 + va3;
        float sb = vb0 + vb1 + vb2 + vb3;
        float qa = fmaf(va0, va0, fmaf(va1, va1, fmaf(va2, va2, va3 * va3)));
        float qb = fmaf(vb0, vb0, fmaf(vb1, vb1, fmaf(vb2, vb2, vb3 * vb3)));
#pragma unroll
        for (int off = 8; off >= 1; off >>= 1) {
            sa += __shfl_xor_sync(0xffffffffu, sa, off, 16);
            sb += __shfl_xor_sync(0xffffffffu, sb, off, 16);
            qa += __shfl_xor_sync(0xffffffffu, qa, off, 16);
            qb += __shfl_xor_sync(0xffffffffu, qb, off, 16);
        }
        float mua = sa * (1.0f / 64.0f);
        float mub = sb * (1.0f / 64.0f);
        float ra  = rsqrtf(qa * (1.0f / 64.0f) - mua * mua + 1e-5f);
        float rb  = rsqrtf(qb * (1.0f / 64.0f) - mub * mub + 1e-5f);

        va0 = gelu_exact((va0 - mua) * ra * gmv.x + btv.x);
        va1 = gelu_exact((va1 - mua) * ra * gmv.y + btv.y);
        va2 = gelu_exact((va2 - mua) * ra * gmv.z + btv.z);
        va3 = gelu_exact((va3 - mua) * ra * gmv.w + btv.w);
        vb0 = gelu_exact((vb0 - mub) * rb * gmv.x + btv.x);
        vb1 = gelu_exact((vb1 - mub) * rb * gmv.y + btv.y);
        vb2 = gelu_exact((vb2 - mub) * rb * gmv.z + btv.z);
        vb3 = gelu_exact((vb3 - mub) * rb * gmv.w + btv.w);

        {
            int vja = jidx[ea];
            float* pa = g_G + (size_t)vja * 64 + c0;
            asm volatile("red.global.add.v4.f32 [%0], {%1,%2,%3,%4};"
                         :: "l"(pa), "f"(va0), "f"(va1), "f"(va2), "f"(va3) : "memory");
            int vjb = jidx[eb];
            float* pb = g_G + (size_t)vjb * 64 + c0;
            asm volatile("red.global.add.v4.f32 [%0], {%1,%2,%3,%4};"
                         :: "l"(pb), "f"(vb0), "f"(vb1), "f"(vb2), "f"(vb3) : "memory");
            if (tx == 0) {
                asm volatile("red.global.add.f32 [%0], %1;"
                             :: "l"(g_degf + vja), "f"(1.0f) : "memory");
                asm volatile("red.global.add.f32 [%0], %1;"
                             :: "l"(g_degf + vjb), "f"(1.0f) : "memory");
            }
        }
    }
}

// ---------------------------------------------------------------------------
// Node kernel: out[n] = G[n] @ W2 + deg[n] * b2, f32x2 channel-pair math.
// 64 nodes per CTA. Thread: c0=(t&7)*8, n0=(t>>3)*2.
__global__ void __launch_bounds__(NTHREADS, 2)
node_kernel(const float* __restrict__ W2,
            const float* __restrict__ b2,
            float* __restrict__ out,
            int N) {
    extern __shared__ float sm[];
    float* GT  = sm;                  // [k][node], stride 65
    float* W2s = sm + 64 * 65 + 4;    // [k][c] 64x64

    int t = threadIdx.x;
    int n_base = blockIdx.x * 64;

#pragma unroll
    for (int it = 0; it < 16; ++it) {
        int idx = t + it * NTHREADS;
        int node = idx >> 6, k = idx & 63;
        int gn = n_base + node;
        GT[k * 65 + node] = (gn < N) ? g_G[(size_t)gn * 64 + k] : 0.f;
        W2s[idx] = W2[idx];
    }
    __syncthreads();

    int tx = t & 7, ty = t >> 3;
    int c0 = tx * 8, n0 = ty * 2;

    // acc[n*4+cp]: node n (0..1), channel-pair cp (0..3)
    ull_t acc[8];
#pragma unroll
    for (int i = 0; i < 8; ++i) acc[i] = 0ull;

#pragma unroll 4
    for (int k = 0; k < 64; ++k) {
        const float* gp = &GT[k * 65 + n0];
        ull_t X0, X1;
        DUP(X0, gp[0]); DUP(X1, gp[1]);
        const ull_t* wp = (const ull_t*)&W2s[k * 64 + c0];
        ulonglong2 w01 = *(const ulonglong2*)(wp);
        ulonglong2 w23 = *(const ulonglong2*)(wp + 2);
        fma2(acc[0], X0, w01.x); fma2(acc[1], X0, w01.y);
        fma2(acc[2], X0, w23.x); fma2(acc[3], X0, w23.y);
        fma2(acc[4], X1, w01.x); fma2(acc[5], X1, w01.y);
        fma2(acc[6], X1, w23.x); fma2(acc[7], X1, w23.y);
    }

    // + deg * b2, store
    ulonglong2 b01, b23;
    {
        const ull_t* bp = (const ull_t*)&b2[c0];
        b01 = *(const ulonglong2*)(bp);
        b23 = *(const ulonglong2*)(bp + 2);
    }
#pragma unroll
    for (int r = 0; r < 2; ++r) {
        int gn = n_base + n0 + r;
        if (gn < N) {
            ull_t D; DUP(D, g_degf[gn]);
            ull_t v0 = acc[r * 4 + 0], v1 = acc[r * 4 + 1];
            ull_t v2 = acc[r * 4 + 2], v3 = acc[r * 4 + 3];
            fma2(v0, D, b01.x); fma2(v1, D, b01.y);
            fma2(v2, D, b23.x); fma2(v3, D, b23.y);
            ull_t* dst = (ull_t*)&out[(size_t)gn * 64 + c0];
            ulonglong2 s01; s01.x = v0; s01.y = v1;
            ulonglong2 s23; s23.x = v2; s23.y = v3;
            *(ulonglong2*)(dst)     = s01;
            *(ulonglong2*)(dst + 2) = s23;
        }
    }
}

// ---------------------------------------------------------------------------
extern "C" void kernel_launch(void* const* d_in, const int* in_sizes, int n_in,
                              void* d_out, int out_size) {
    const float* x          = (const float*)d_in[0];
    const void*  edge_index = d_in[1];
    const float* edge_attr  = (const float*)d_in[2];
    const float* W1         = (const float*)d_in[3];
    const float* b1         = (const float*)d_in[4];
    const float* gamma      = (const float*)d_in[5];
    const float* beta       = (const float*)d_in[6];
    const float* W2         = (const float*)d_in[7];
    const float* b2         = (const float*)d_in[8];
    float*       out        = (float*)d_out;

    int N = in_sizes[0] / 64;     // 100000
    int E = in_sizes[2] / 32;     // 1600000

    const int SM_PRE  = (64 * 65 + 4 + 64 * 128) * 4;
    const int SM_EDGE = 26112;
    const int SM_NODE = (64 * 65 + 4 + 64 * 64) * 4;
    cudaFuncSetAttribute(precompute_kernel, cudaFuncAttributeMaxDynamicSharedMemorySize, SM_PRE);
    cudaFuncSetAttribute(edge_kernel,       cudaFuncAttributeMaxDynamicSharedMemorySize, SM_EDGE);
    cudaFuncSetAttribute(node_kernel,       cudaFuncAttributeMaxDynamicSharedMemorySize, SM_NODE);

    precompute_kernel<<<(N + 63) / 64, NTHREADS, SM_PRE>>>(x, W1, b1, edge_index, N);
    edge_kernel<<<E / E_TILE, NTHREADS, SM_EDGE>>>(edge_index, edge_attr, W1,
                                                   gamma, beta, E);
    node_kernel<<<(N + 63) / 64, NTHREADS, SM_NODE>>>(W2, b2, out, N);
}

// round 10
// speedup vs baseline: 1.1183x; 1.1183x over previous
#include <cuda_runtime.h>
#include <cstdint>
#include <cstddef>

// ---------------------------------------------------------------------------
// MPConv fused GNN edge-MLP + scatter on GB300 (sm_103a)
// R10 = R8 (proven: scalar-FMA precompute/node, raw-weight FFMA2 edge GEMM,
//       coalesced gather/scatter mapping) + edge E_TILE=256 as two sequential
//       128-edge halves sharing one staging pass.
// ---------------------------------------------------------------------------

#define NODES_MAX 100000
#define E_TILE    256
#define NTHREADS  256

typedef unsigned long long ull_t;

__device__ __align__(16) float g_AB[(size_t)NODES_MAX * 128];   // A||B per node
__device__ __align__(16) float g_G[(size_t)NODES_MAX * 64];     // scattered g sums
__device__ __align__(16) float g_degf[NODES_MAX];               // edge counts
__device__ int g_idx64;

__device__ __forceinline__ float gelu_exact(float v) {
    return 0.5f * v * (1.0f + erff(v * 0.70710678118654752440f));
}

__device__ __forceinline__ void fma2(ull_t& d, ull_t a, ull_t b) {
    asm("fma.rn.f32x2 %0, %1, %2, %0;" : "+l"(d) : "l"(a), "l"(b));
}
#define UNPK(lo, hi, v) asm("mov.b64 {%0,%1}, %2;" : "=f"(lo), "=f"(hi) : "l"(v))
#define DUP(d, f)       asm("mov.b64 %0, {%1, %1};" : "=l"(d) : "f"(f))

// ---------------------------------------------------------------------------
// parallel dtype detect (separate tiny kernel, race-free)
__global__ void detect_idx_kernel(const void* edge_index, int N) {
    __shared__ int s_bad;
    int t = threadIdx.x;
    if (t == 0) s_bad = 0;
    __syncthreads();
    long long v = ((const long long*)edge_index)[t];
    if (v < 0 || v >= (long long)N) atomicOr(&s_bad, 1);
    __syncthreads();
    if (t == 0) g_idx64 = !s_bad;
}

__device__ __forceinline__ int load_edge_idx(const void* ei, long long pos, int idx64) {
    if (idx64) return (int)((const long long*)ei)[pos];
    return ((const int*)ei)[pos];
}

// ---------------------------------------------------------------------------
#define FMA_ROW(ACC, A, B)                          \
    ACC.x = fmaf((A), (B).x, ACC.x);                \
    ACC.y = fmaf((A), (B).y, ACC.y);                \
    ACC.z = fmaf((A), (B).z, ACC.z);                \
    ACC.w = fmaf((A), (B).w, ACC.w);

// Precompute g_AB + zero this block's slice of g_G / g_degf. (R8-proven)
__global__ void __launch_bounds__(NTHREADS, 2)
precompute_kernel(const float* __restrict__ x,
                  const float* __restrict__ W1,
                  const float* __restrict__ b1,
                  int N) {
    extern __shared__ float sm[];
    float* xT = sm;                  // [k][node], stride 65
    float* Wc = sm + 64 * 65 + 4;    // [k][c] 64x128

    int t = threadIdx.x;
    int n_base = blockIdx.x * 64;

    // zero scratch for this block's nodes
    {
        float4 z4 = make_float4(0.f, 0.f, 0.f, 0.f);
#pragma unroll
        for (int it = 0; it < 4; ++it) {
            int idx = t + it * NTHREADS;        // 0..1023 float4 slots
            int node = idx >> 4, q = idx & 15;
            int gn = n_base + node;
            if (gn < N) ((float4*)g_G)[(size_t)gn * 16 + q] = z4;
        }
        if (t < 64 && n_base + t < N) g_degf[n_base + t] = 0.f;
    }

#pragma unroll
    for (int it = 0; it < 32; ++it) {
        int idx = t + it * NTHREADS;
        int k = idx >> 7, c = idx & 127;
        Wc[idx] = (c < 64) ? W1[k * 64 + c] : W1[(64 + k) * 64 + (c - 64)];
    }
#pragma unroll
    for (int it = 0; it < 16; ++it) {
        int idx = t + it * NTHREADS;
        int node = idx >> 6, k = idx & 63;
        int gn = n_base + node;
        xT[k * 65 + node] = (gn < N) ? x[(size_t)gn * 64 + k] : 0.f;
    }
    __syncthreads();

    int tx = t & 31, ty = t >> 5;
    int c0 = tx * 4, n0 = ty * 8;

    float4 acc[8];
#pragma unroll
    for (int r = 0; r < 8; ++r) acc[r] = make_float4(0.f, 0.f, 0.f, 0.f);

#pragma unroll 8
    for (int k = 0; k < 64; ++k) {
        float4 b = *(const float4*)&Wc[k * 128 + c0];
        const float* xp = &xT[k * 65 + n0];
#pragma unroll
        for (int r = 0; r < 8; ++r) { FMA_ROW(acc[r], xp[r], b); }
    }

    float4 badd = make_float4(0.f, 0.f, 0.f, 0.f);
    if (c0 < 64) badd = *(const float4*)&b1[c0];

#pragma unroll
    for (int r = 0; r < 8; ++r) {
        int gn = n_base + n0 + r;
        if (gn < N) {
            float4 v = acc[r];
            v.x += badd.x; v.y += badd.y; v.z += badd.z; v.w += badd.w;
            *(float4*)&g_AB[(size_t)gn * 128 + c0] = v;
        }
    }
}

// ---------------------------------------------------------------------------
// Edge kernel. 256 edges/block staged once, processed as two 128-edge halves
// with the R8-proven inner loop (4ch x 8edge per thread per half).
// dyn smem (44544 B):
//   iidx[256] @0 (1024), jidx[256] @1024 (1024)
//   W1p [32][64] f32 raw @2048  (8192)
//   eaT [32][268] f32    @10240 (34304)   stride 268: 16B-aligned, 4-way STS
__global__ void __launch_bounds__(NTHREADS, 3)
edge_kernel(const void* __restrict__ edge_index,
            const float* __restrict__ edge_attr,
            const float* __restrict__ W1,
            const float* __restrict__ gamma,
            const float* __restrict__ beta,
            int E) {
    extern __shared__ char smraw[];
    int*   iidx = (int*)smraw;
    int*   jidx = (int*)(smraw + 1024);
    float* W1p  = (float*)(smraw + 2048);
    float* eaT  = (float*)(smraw + 10240);

    int t = threadIdx.x;
    long long e_base = (long long)blockIdx.x * E_TILE;
    int idx64 = g_idx64;

    // edge indices (E multiple of 256)
    iidx[t] = load_edge_idx(edge_index, e_base + t, idx64);
    jidx[t] = load_edge_idx(edge_index, (long long)E + e_base + t, idx64);

    // W1p: raw copy of W1 rows 128..159 (2048 floats = 512 float4)
    {
        const float4* src = (const float4*)(W1 + 128 * 64);
        float4* dst = (float4*)W1p;
        dst[t]       = src[t];
        dst[t + 256] = src[t + 256];
    }
    // edge_attr transposed: eaT[k][e], stride 268, 256 edges
    {
        const float4* ea4 = (const float4*)edge_attr;
#pragma unroll
        for (int it = 0; it < 8; ++it) {
            int slot = t + it * NTHREADS;           // 0..2047
            int e = slot >> 3, q = slot & 7;
            float4 v = ea4[e_base * 8 + slot];
            int k = q * 4;
            eaT[(k + 0) * 268 + e] = v.x;
            eaT[(k + 1) * 268 + e] = v.y;
            eaT[(k + 2) * 268 + e] = v.z;
            eaT[(k + 3) * 268 + e] = v.w;
        }
    }
    __syncthreads();

    int tx = t & 15, ty = t >> 4;
    int c0 = tx * 4;

    float4 gmv = *(const float4*)&gamma[c0];
    float4 btv = *(const float4*)&beta[c0];
    const float4* AB4 = (const float4*)g_AB;

#pragma unroll 1
    for (int half = 0; half < 2; ++half) {
        int e0 = half * 128 + ty * 8;

        // acc[c*4+p]: channel c (0..3), edge-pair p (0..3)
        ull_t acc[16];
#pragma unroll
        for (int i = 0; i < 16; ++i) acc[i] = 0ull;

        // -------- GEMM1: h = ea @ W1c (raw weight LDS.128 + reg dup) --------
#pragma unroll 4
        for (int kk = 0; kk < 32; ++kk) {
            float4 w = *(const float4*)&W1p[kk * 64 + c0];
            ull_t W0, W1r, W2r, W3r;
            DUP(W0, w.x); DUP(W1r, w.y); DUP(W2r, w.z); DUP(W3r, w.w);
            const float* ap = eaT + kk * 268 + e0;
            ulonglong2 A01 = *(const ulonglong2*)(ap);
            ulonglong2 A23 = *(const ulonglong2*)(ap + 4);
            fma2(acc[ 0], A01.x, W0);  fma2(acc[ 1], A01.y, W0);
            fma2(acc[ 2], A23.x, W0);  fma2(acc[ 3], A23.y, W0);
            fma2(acc[ 4], A01.x, W1r); fma2(acc[ 5], A01.y, W1r);
            fma2(acc[ 6], A23.x, W1r); fma2(acc[ 7], A23.y, W1r);
            fma2(acc[ 8], A01.x, W2r); fma2(acc[ 9], A01.y, W2r);
            fma2(acc[10], A23.x, W2r); fma2(acc[11], A23.y, W2r);
            fma2(acc[12], A01.x, W3r); fma2(acc[13], A01.y, W3r);
            fma2(acc[14], A23.x, W3r); fma2(acc[15], A23.y, W3r);
        }

        // -------- epilogue, pair-by-pair --------
#pragma unroll
        for (int p = 0; p < 4; ++p) {
            int ea = e0 + 2 * p, eb = ea + 1;

            float va0, vb0, va1, vb1, va2, vb2, va3, vb3;
            UNPK(va0, vb0, acc[0 * 4 + p]);
            UNPK(va1, vb1, acc[1 * 4 + p]);
            UNPK(va2, vb2, acc[2 * 4 + p]);
            UNPK(va3, vb3, acc[3 * 4 + p]);

            {
                float4 Aa = AB4[(size_t)iidx[ea] * 32 + tx];
                float4 Ba = AB4[(size_t)jidx[ea] * 32 + 16 + tx];
                va0 += Aa.x + Ba.x; va1 += Aa.y + Ba.y;
                va2 += Aa.z + Ba.z; va3 += Aa.w + Ba.w;
            }
            {
                float4 Ab = AB4[(size_t)iidx[eb] * 32 + tx];
                float4 Bb = AB4[(size_t)jidx[eb] * 32 + 16 + tx];
                vb0 += Ab.x + Bb.x; vb1 += Ab.y + Bb.y;
                vb2 += Ab.z + Bb.z; vb3 += Ab.w + Bb.w;
            }

            float sa = va0 + va1 + va2 + va3;
            float sb = vb0 + vb1 + vb2 + vb3;
            float qa = fmaf(va0, va0, fmaf(va1, va1, fmaf(va2, va2, va3 * va3)));
            float qb = fmaf(vb0, vb0, fmaf(vb1, vb1, fmaf(vb2, vb2, vb3 * vb3)));
#pragma unroll
            for (int off = 8; off >= 1; off >>= 1) {
                sa += __shfl_xor_sync(0xffffffffu, sa, off, 16);
                sb += __shfl_xor_sync(0xffffffffu, sb, off, 16);
                qa += __shfl_xor_sync(0xffffffffu, qa, off, 16);
                qb += __shfl_xor_sync(0xffffffffu, qb, off, 16);
            }
            float mua = sa * (1.0f / 64.0f);
            float mub = sb * (1.0f / 64.0f);
            float ra  = rsqrtf(qa * (1.0f / 64.0f) - mua * mua + 1e-5f);
            float rb  = rsqrtf(qb * (1.0f / 64.0f) - mub * mub + 1e-5f);

            va0 = gelu_exact((va0 - mua) * ra * gmv.x + btv.x);
            va1 = gelu_exact((va1 - mua) * ra * gmv.y + btv.y);
            va2 = gelu_exact((va2 - mua) * ra * gmv.z + btv.z);
            va3 = gelu_exact((va3 - mua) * ra * gmv.w + btv.w);
            vb0 = gelu_exact((vb0 - mub) * rb * gmv.x + btv.x);
            vb1 = gelu_exact((vb1 - mub) * rb * gmv.y + btv.y);
            vb2 = gelu_exact((vb2 - mub) * rb * gmv.z + btv.z);
            vb3 = gelu_exact((vb3 - mub) * rb * gmv.w + btv.w);

            {
                int vja = jidx[ea];
                float* pa = g_G + (size_t)vja * 64 + c0;
                asm volatile("red.global.add.v4.f32 [%0], {%1,%2,%3,%4};"
                             :: "l"(pa), "f"(va0), "f"(va1), "f"(va2), "f"(va3) : "memory");
                int vjb = jidx[eb];
                float* pb = g_G + (size_t)vjb * 64 + c0;
                asm volatile("red.global.add.v4.f32 [%0], {%1,%2,%3,%4};"
                             :: "l"(pb), "f"(vb0), "f"(vb1), "f"(vb2), "f"(vb3) : "memory");
                if (tx == 0) {
                    asm volatile("red.global.add.f32 [%0], %1;"
                                 :: "l"(g_degf + vja), "f"(1.0f) : "memory");
                    asm volatile("red.global.add.f32 [%0], %1;"
                                 :: "l"(g_degf + vjb), "f"(1.0f) : "memory");
                }
            }
        }
    }
}

// ---------------------------------------------------------------------------
// Node kernel: out[n] = G[n] @ W2 + deg[n] * b2. 64 nodes per CTA. (R8-proven)
__global__ void __launch_bounds__(NTHREADS, 2)
node_kernel(const float* __restrict__ W2,
            const float* __restrict__ b2,
            float* __restrict__ out,
            int N) {
    extern __shared__ float sm[];
    float* GT  = sm;                  // [k][node], stride 65
    float* W2s = sm + 64 * 65 + 4;    // [k][c] 64x64

    int t = threadIdx.x;
    int n_base = blockIdx.x * 64;

#pragma unroll
    for (int it = 0; it < 16; ++it) {
        int idx = t + it * NTHREADS;
        int node = idx >> 6, k = idx & 63;
        int gn = n_base + node;
        GT[k * 65 + node] = (gn < N) ? g_G[(size_t)gn * 64 + k] : 0.f;
        W2s[idx] = W2[idx];
    }
    __syncthreads();

    int tx = t & 15, ty = t >> 4;
    int c0 = tx * 4, n0 = ty * 4;

    float4 acc[4];
#pragma unroll
    for (int r = 0; r < 4; ++r) acc[r] = make_float4(0.f, 0.f, 0.f, 0.f);

#pragma unroll 8
    for (int k = 0; k < 64; ++k) {
        float4 b = *(const float4*)&W2s[k * 64 + c0];
        const float* gpv = &GT[k * 65 + n0];
#pragma unroll
        for (int r = 0; r < 4; ++r) { FMA_ROW(acc[r], gpv[r], b); }
    }

    float4 b2v = *(const float4*)&b2[c0];
#pragma unroll
    for (int r = 0; r < 4; ++r) {
        int gn = n_base + n0 + r;
        if (gn < N) {
            float d = g_degf[gn];
            float4 v = acc[r];
            v.x = fmaf(d, b2v.x, v.x); v.y = fmaf(d, b2v.y, v.y);
            v.z = fmaf(d, b2v.z, v.z); v.w = fmaf(d, b2v.w, v.w);
            *(float4*)&out[(size_t)gn * 64 + c0] = v;
        }
    }
}

// ---------------------------------------------------------------------------
extern "C" void kernel_launch(void* const* d_in, const int* in_sizes, int n_in,
                              void* d_out, int out_size) {
    const float* x          = (const float*)d_in[0];
    const void*  edge_index = d_in[1];
    const float* edge_attr  = (const float*)d_in[2];
    const float* W1         = (const float*)d_in[3];
    const float* b1         = (const float*)d_in[4];
    const float* gamma      = (const float*)d_in[5];
    const float* beta       = (const float*)d_in[6];
    const float* W2         = (const float*)d_in[7];
    const float* b2         = (const float*)d_in[8];
    float*       out        = (float*)d_out;

    int N = in_sizes[0] / 64;     // 100000
    int E = in_sizes[2] / 32;     // 1600000

    const int SM_PRE  = (64 * 65 + 4 + 64 * 128) * 4;
    const int SM_EDGE = 44544;
    const int SM_NODE = (64 * 65 + 4 + 64 * 64) * 4;
    cudaFuncSetAttribute(precompute_kernel, cudaFuncAttributeMaxDynamicSharedMemorySize, SM_PRE);
    cudaFuncSetAttribute(edge_kernel,       cudaFuncAttributeMaxDynamicSharedMemorySize, SM_EDGE);
    cudaFuncSetAttribute(node_kernel,       cudaFuncAttributeMaxDynamicSharedMemorySize, SM_NODE);

    detect_idx_kernel<<<1, 128>>>(edge_index, N);
    precompute_kernel<<<(N + 63) / 64, NTHREADS, SM_PRE>>>(x, W1, b1, N);
    edge_kernel<<<E / E_TILE, NTHREADS, SM_EDGE>>>(edge_index, edge_attr, W1,
                                                   gamma, beta, E);
    node_kernel<<<(N + 63) / 64, NTHREADS, SM_NODE>>>(W2, b2, out, N);
}